// round 15
// baseline (speedup 1.0000x reference)
#include <cuda_runtime.h>

#define S      256
#define NB     128
#define L      256
#define NL     64
#define VOCAB  32000

typedef unsigned long long ull;

// K1 dynamic smem:
//   TsmU2 [24][256] ulonglong2 = 98304 B  (T tail: 2 states x 48 j floats/thread)
//   xs    [2][2][256] float    =  4096 B  (double-buffered state vec per chain)
//   part  [2][2][2][256] float =  8192 B  (DOUBLE-BUFFERED partials [p][c][h][s])
//   tok   [2][256] int         =  2048 B
#define SMEM1  (98304 + 4096 + 8192 + 2048)

// K2 dynamic smem: esmd ull[128][66] + osm float[64][64]
#define SMEM2  (128*66*8 + 64*64*4)

// scratch
__device__ float g_fwd[L * NB * S];   // fprime[t][b][s]  (pre-e-multiply forward)
__device__ float g_bwd[L * NB * S];   // b[t][b][s]

__device__ __forceinline__ void ffma2(ull &a, ull b, ull c) {
    asm("fma.rn.f32x2 %0, %1, %2, %0;" : "+l"(a) : "l"(b), "l"(c));
}
__device__ __forceinline__ float hsum2(ull lo, ull hi) {
    float2 a = *reinterpret_cast<float2*>(&lo);
    float2 b = *reinterpret_cast<float2*>(&hi);
    return (a.x + a.y) + (b.x + b.y);
}
__device__ __forceinline__ ull packdup(float e) {
    ull r;
    asm("mov.b64 %0, {%1, %1};" : "=l"(r) : "f"(e));
    return r;
}
#define BARS(id, cnt) asm volatile("bar.sync %0, %1;" :: "r"(id), "r"(cnt) : "memory")

// ---------------------------------------------------------------------------
// K1 (R12 dataflow; FULL barriers replaced by minimal named barriers):
// 128 CTAs x 256 threads, 2 chains/CTA. bid<64: fwd batches (2p,2p+1);
// bid>=64: bwd. Thread (h=tid>>7, u=tid&127) owns states {u, u+128},
// j in [128h, 128h+128), T split 80 reg / 48 smem floats per state.
// bar1: pairwise (warp w <-> w+4, 64 threads) — partial producer/consumer.
// bar2: per j-half (128 threads) — x producer/consumer stay in-group.
// part[] double-buffered to close the cross-step reuse race.
// ---------------------------------------------------------------------------
__global__ __launch_bounds__(256, 1)
void hmm_scan_kernel(const void* __restrict__ sent_raw,
                     const float* __restrict__ emb,
                     const float* __restrict__ Tm)
{
    extern __shared__ char smem_raw[];
    ulonglong2* TsmU2 = (ulonglong2*)smem_raw;               // [24][256]
    float* xs   = (float*)(smem_raw + 98304);                // [p][c][256]
    float* part = (float*)(smem_raw + 98304 + 4096);         // [p][c][h][256]
    int*   tok  = (int*)  (smem_raw + 98304 + 4096 + 8192);  // [c][256]
    __shared__ int s_i64;

    const int  tid = threadIdx.x;
    const int  w   = tid >> 5;
    const int  h   = tid >> 7;
    const int  u   = tid & 127;
    const int  j0  = h << 7;
    const int  bid = blockIdx.x;
    const bool bwd = (bid >= 64);
    const int  b0  = (bid & 63) * 2;
    const int  b1  = b0 + 1;
    const int  bar1_id = 1 + (w & 3);    // pairs {w, w+4}
    const int  bar2_id = 5 + h;          // per j-half group

    // --- detect sentences dtype (int64 vs int32) ---
    if (tid == 0) {
        const long long* s64 = (const long long*)sent_raw;
        int f = 1;
        for (int k = 0; k < 64; k++) {
            long long v = s64[k];
            if (v < 0 || v >= VOCAB) { f = 0; break; }
        }
        s_i64 = f;
    }
    __syncthreads();

    // --- tokens for both chains ---
    if (s_i64) {
        const long long* s64 = (const long long*)sent_raw;
        tok[tid]       = (int)s64[b0 * L + tid];
        tok[256 + tid] = (int)s64[b1 * L + tid];
    } else {
        const int* s32 = (const int*)sent_raw;
        tok[tid]       = s32[b0 * L + tid];
        tok[256 + tid] = s32[b1 * L + tid];
    }

    // --- T slices: states u (A) / u+128 (B), j in [j0, j0+128):
    //     80 floats in regs (40 ull) + 48 floats in smem (12 u2) per state ---
    ull TrA[40], TrB[40];
    if (!bwd) {
        const float4* rowA = (const float4*)(Tm + u * S + j0);
        const float4* rowB = (const float4*)(Tm + (u + 128) * S + j0);
        #pragma unroll
        for (int g = 0; g < 20; g++) {
            ((float4*)TrA)[g] = rowA[g];
            ((float4*)TrB)[g] = rowB[g];
        }
        #pragma unroll
        for (int g = 0; g < 12; g++) {
            TsmU2[g * 256 + tid]        = ((const ulonglong2*)rowA)[20 + g];
            TsmU2[(12 + g) * 256 + tid] = ((const ulonglong2*)rowB)[20 + g];
        }
    } else {
        #pragma unroll
        for (int g = 0; g < 20; g++) {
            int j = j0 + 4 * g;
            ((float4*)TrA)[g] = make_float4(Tm[(j+0)*S + u],       Tm[(j+1)*S + u],
                                            Tm[(j+2)*S + u],       Tm[(j+3)*S + u]);
            ((float4*)TrB)[g] = make_float4(Tm[(j+0)*S + u + 128], Tm[(j+1)*S + u + 128],
                                            Tm[(j+2)*S + u + 128], Tm[(j+3)*S + u + 128]);
        }
        #pragma unroll
        for (int g = 0; g < 12; g++) {
            int j = j0 + 80 + 4 * g;
            float4 a4 = make_float4(Tm[(j+0)*S + u],       Tm[(j+1)*S + u],
                                    Tm[(j+2)*S + u],       Tm[(j+3)*S + u]);
            float4 b4 = make_float4(Tm[(j+0)*S + u + 128], Tm[(j+1)*S + u + 128],
                                    Tm[(j+2)*S + u + 128], Tm[(j+3)*S + u + 128]);
            TsmU2[g * 256 + tid]        = *reinterpret_cast<ulonglong2*>(&a4);
            TsmU2[(12 + g) * 256 + tid] = *reinterpret_cast<ulonglong2*>(&b4);
        }
    }

    float* outg = bwd ? g_bwd : g_fwd;

    // --- step 0 ---
    const int t0 = bwd ? (L - 1) : 0;
    {
        float e0 = emb[tok[t0] * S + tid];
        float e1 = emb[tok[256 + t0] * S + tid];
        if (!bwd) {
            outg[(t0 * NB + b0) * S + tid] = 1.0f;    // fprime[0] = 1
            outg[(t0 * NB + b1) * S + tid] = 1.0f;
        } else {
            outg[(t0 * NB + b0) * S + tid] = e0;      // b[L-1] = e[L-1]
            outg[(t0 * NB + b1) * S + tid] = e1;
        }
        xs[tid]       = e0;
        xs[256 + tid] = e1;
    }
    __syncthreads();

    const int dt = bwd ? -1 : 1;
    int t = t0;
    int p = 0;

    float o0 = 0.f, o1 = 0.f;
    int   tprev = -1;

    for (int step = 1; step < L; step++) {
        t += dt;

        // deferred output write from previous step (overlaps this matvec)
        if (tprev >= 0) {
            outg[(tprev * NB + b0) * S + tid] = o0;
            outg[(tprev * NB + b1) * S + tid] = o1;
        }

        // e prefetch: consumed only after bar1
        float en0 = emb[tok[t] * S + tid];
        float en1 = emb[tok[256 + t] * S + tid];

        const ulonglong2* X0 = (const ulonglong2*)(xs + p * 512 + j0);
        const ulonglong2* X1 = (const ulonglong2*)(xs + p * 512 + 256 + j0);

        ull a00l = 0, a00h = 0, a01l = 0, a01h = 0;   // state u:     chain0, chain1
        ull a10l = 0, a10h = 0, a11l = 0, a11h = 0;   // state u+128

        #pragma unroll
        for (int g = 0; g < 20; g++) {
            ulonglong2 x0 = X0[g];
            ulonglong2 x1 = X1[g];
            ffma2(a00l, TrA[2*g],   x0.x); ffma2(a00h, TrA[2*g+1], x0.y);
            ffma2(a01l, TrA[2*g],   x1.x); ffma2(a01h, TrA[2*g+1], x1.y);
            ffma2(a10l, TrB[2*g],   x0.x); ffma2(a10h, TrB[2*g+1], x0.y);
            ffma2(a11l, TrB[2*g],   x1.x); ffma2(a11h, TrB[2*g+1], x1.y);
        }
        #pragma unroll
        for (int g = 0; g < 12; g++) {
            ulonglong2 tA = TsmU2[g * 256 + tid];
            ulonglong2 tB = TsmU2[(12 + g) * 256 + tid];
            ulonglong2 x0 = X0[20 + g];
            ulonglong2 x1 = X1[20 + g];
            ffma2(a00l, tA.x, x0.x); ffma2(a00h, tA.y, x0.y);
            ffma2(a01l, tA.x, x1.x); ffma2(a01h, tA.y, x1.y);
            ffma2(a10l, tB.x, x0.x); ffma2(a10h, tB.y, x0.y);
            ffma2(a11l, tB.x, x1.x); ffma2(a11h, tB.y, x1.y);
        }

        // partials into buffer p: part[p][c][h][s]
        float* pp = part + p * 1024;
        pp[h * 256 + u]             = hsum2(a00l, a00h);
        pp[h * 256 + u + 128]       = hsum2(a10l, a10h);
        pp[512 + h * 256 + u]       = hsum2(a01l, a01h);
        pp[512 + h * 256 + u + 128] = hsum2(a11l, a11h);
        BARS(bar1_id, 64);                 // sync producer/consumer pair only

        // combine: thread tid handles state tid, both chains
        float s0 = pp[tid]       + pp[256 + tid];
        float s1 = pp[512 + tid] + pp[768 + tid];
        float nx0 = s0 * en0;
        float nx1 = s1 * en1;

        o0 = bwd ? nx0 : s0;
        o1 = bwd ? nx1 : s1;
        tprev = t;

        p ^= 1;
        xs[p * 512 + tid]       = nx0;
        xs[p * 512 + 256 + tid] = nx1;
        BARS(bar2_id, 128);                // x stays within the j-half group
    }

    // final deferred write
    outg[(tprev * NB + b0) * S + tid] = o0;
    outg[(tprev * NB + b1) * S + tid] = o1;
}

// ---------------------------------------------------------------------------
// K2 v4: 256 CTAs, tile = 128 rows x 64 cols, 8x4 per thread.
// e stored PRE-DUPLICATED in smem as (e,e) ull pairs -> the hot loop loses
// all packdups (58 -> 42 instr per 2-sc iteration).
// ---------------------------------------------------------------------------
__global__ __launch_bounds__(256, 2)
void hmm_proj_kernel(const float* __restrict__ Om, float* __restrict__ outp)
{
    extern __shared__ char smem2[];
    ull*   esmd = (ull*)smem2;                     // [128][66] (row stride 66)
    float* osm  = (float*)(smem2 + 128*66*8);      // [64][64]

    const int tid = threadIdx.x;
    const int r0  = blockIdx.x * 128;
    const int rg  = tid >> 4;
    const int cg  = tid & 15;

    ull acc01[8] = {0,0,0,0,0,0,0,0};
    ull acc23[8] = {0,0,0,0,0,0,0,0};

    for (int s0 = 0; s0 < S; s0 += 64) {
        if (s0) __syncthreads();
        // E = fprime*b, stored duplicated: esmd[row][sc] = (e,e)
        #pragma unroll
        for (int k = 0; k < 8; k++) {
            int id4 = k * 256 + tid;
            int rr  = id4 >> 4;
            int ss  = (id4 & 15) * 4;            // ull index within row
            int r   = r0 + rr;
            float4 fv = *(const float4*)&g_fwd[r * S + s0 + ss];
            float4 bv = *(const float4*)&g_bwd[r * S + s0 + ss];
            ull d0 = packdup(fv.x * bv.x);
            ull d1 = packdup(fv.y * bv.y);
            ull d2 = packdup(fv.z * bv.z);
            ull d3 = packdup(fv.w * bv.w);
            *(ulonglong2*)&esmd[rr * 66 + ss]     = make_ulonglong2(d0, d1);
            *(ulonglong2*)&esmd[rr * 66 + ss + 2] = make_ulonglong2(d2, d3);
        }
        #pragma unroll
        for (int k = 0; k < 4; k++) {
            int id4 = k * 256 + tid;
            int ss  = id4 >> 4;
            int n   = (id4 & 15) * 4;
            *(float4*)&osm[ss * 64 + n] = *(const float4*)&Om[(s0 + ss) * NL + n];
        }
        __syncthreads();

        #pragma unroll 4
        for (int sc = 0; sc < 64; sc += 2) {
            ulonglong2 ov0 = *(const ulonglong2*)&osm[sc * 64 + cg * 4];
            ulonglong2 ov1 = *(const ulonglong2*)&osm[(sc + 1) * 64 + cg * 4];
            #pragma unroll
            for (int k = 0; k < 8; k++) {
                ulonglong2 ee = *(const ulonglong2*)&esmd[(rg * 8 + k) * 66 + sc];
                ffma2(acc01[k], ee.x, ov0.x);
                ffma2(acc23[k], ee.x, ov0.y);
                ffma2(acc01[k], ee.y, ov1.x);
                ffma2(acc23[k], ee.y, ov1.y);
            }
        }
    }

    #pragma unroll
    for (int k = 0; k < 8; k++) {
        int r  = r0 + rg * 8 + k;
        int t  = r >> 7;
        int bb = r & 127;
        float2 lo = *reinterpret_cast<float2*>(&acc01[k]);
        float2 hi = *reinterpret_cast<float2*>(&acc23[k]);
        float4 v  = make_float4(lo.x, lo.y, hi.x, hi.y);
        *(float4*)&outp[(bb * L + t) * NL + cg * 4] = v;
    }
}

extern "C" void kernel_launch(void* const* d_in, const int* in_sizes, int n_in,
                              void* d_out, int out_size)
{
    (void)in_sizes; (void)n_in; (void)out_size;
    const void*  sent = d_in[0];
    const float* emb  = (const float*)d_in[1];
    const float* Tm   = (const float*)d_in[2];
    const float* Om   = (const float*)d_in[3];
    float* outp = (float*)d_out;

    cudaFuncSetAttribute(hmm_scan_kernel,
                         cudaFuncAttributeMaxDynamicSharedMemorySize, SMEM1);
    cudaFuncSetAttribute(hmm_proj_kernel,
                         cudaFuncAttributeMaxDynamicSharedMemorySize, SMEM2);

    hmm_scan_kernel<<<128, 256, SMEM1>>>(sent, emb, Tm);
    hmm_proj_kernel<<<256, 256, SMEM2>>>(Om, outp);
}

// round 16
// speedup vs baseline: 1.0689x; 1.0689x over previous
#include <cuda_runtime.h>

#define S      256
#define NB     128
#define L      256
#define NL     64
#define VOCAB  32000

typedef unsigned long long ull;

// K1 dynamic smem (R6 layout):
//   TsmU2 [16][256] ulonglong2 = 65536 B   (T tail: 2 states x 32 j per thread)
//   xs    [2][2][256] float    =  4096 B   (double-buffered state vec per chain)
//   part  [2][2][256] float    =  4096 B   (partials: [chain][half][state])
//   tok   [2][256] int         =  2048 B
#define SMEM1  (65536 + 4096 + 4096 + 2048)

// K2 dynamic smem: esm[128][68] + osm[64][64]
#define SMEM2  (128*68*4 + 64*64*4)

// scratch
__device__ float g_fwd[L * NB * S];   // fprime[t][b][s]  (pre-e-multiply forward)
__device__ float g_bwd[L * NB * S];   // b[t][b][s]

__device__ __forceinline__ void ffma2(ull &a, ull b, ull c) {
    asm("fma.rn.f32x2 %0, %1, %2, %0;" : "+l"(a) : "l"(b), "l"(c));
}
__device__ __forceinline__ float hsum2(ull lo, ull hi) {
    float2 a = *reinterpret_cast<float2*>(&lo);
    float2 b = *reinterpret_cast<float2*>(&hi);
    return (a.x + a.y) + (b.x + b.y);
}
__device__ __forceinline__ ull packdup(float e) {
    ull r;
    asm("mov.b64 %0, {%1, %1};" : "=l"(r) : "f"(e));
    return r;
}

// ---------------------------------------------------------------------------
// K1 — R6 exact (fastest measured: 289.6us): 128 CTAs x 256 threads,
// 2 chains/CTA. bid<64: fwd batches (2p,2p+1); bid>=64: bwd.
// Thread (h=tid>>7, u=tid&127) owns states {u, u+128}, j in [128h, 128h+128),
// T split 96 reg / 32 smem floats per state. Packed fma.rn.f32x2;
// smem partials; 2 full barriers/step; deferred output STG.
// ---------------------------------------------------------------------------
__global__ __launch_bounds__(256, 1)
void hmm_scan_kernel(const void* __restrict__ sent_raw,
                     const float* __restrict__ emb,
                     const float* __restrict__ Tm)
{
    extern __shared__ char smem_raw[];
    ulonglong2* TsmU2 = (ulonglong2*)smem_raw;              // [16][256]
    float* xs   = (float*)(smem_raw + 65536);               // [p][c][256]
    float* part = (float*)(smem_raw + 65536 + 4096);        // [c][h][256]
    int*   tok  = (int*)  (smem_raw + 65536 + 8192);        // [c][256]
    __shared__ int s_i64;

    const int  tid = threadIdx.x;
    const int  h   = tid >> 7;
    const int  u   = tid & 127;
    const int  j0  = h << 7;
    const int  bid = blockIdx.x;
    const bool bwd = (bid >= 64);
    const int  b0  = (bid & 63) * 2;
    const int  b1  = b0 + 1;

    // --- detect sentences dtype (int64 vs int32) ---
    if (tid == 0) {
        const long long* s64 = (const long long*)sent_raw;
        int f = 1;
        for (int k = 0; k < 64; k++) {
            long long v = s64[k];
            if (v < 0 || v >= VOCAB) { f = 0; break; }
        }
        s_i64 = f;
    }
    __syncthreads();

    // --- tokens for both chains ---
    if (s_i64) {
        const long long* s64 = (const long long*)sent_raw;
        tok[tid]       = (int)s64[b0 * L + tid];
        tok[256 + tid] = (int)s64[b1 * L + tid];
    } else {
        const int* s32 = (const int*)sent_raw;
        tok[tid]       = s32[b0 * L + tid];
        tok[256 + tid] = s32[b1 * L + tid];
    }

    // --- T slices: states u (A) and u+128 (B), j in [j0, j0+128):
    //     96 floats in regs (48 ull), 32 floats in smem (8 ulonglong2) each ---
    ull TrA[48], TrB[48];
    if (!bwd) {
        const float4* rowA = (const float4*)(Tm + u * S + j0);
        const float4* rowB = (const float4*)(Tm + (u + 128) * S + j0);
        #pragma unroll
        for (int g = 0; g < 24; g++) {
            ((float4*)TrA)[g] = rowA[g];
            ((float4*)TrB)[g] = rowB[g];
        }
        #pragma unroll
        for (int g = 0; g < 8; g++) {
            TsmU2[g * 256 + tid]       = ((const ulonglong2*)rowA)[24 + g];
            TsmU2[(8 + g) * 256 + tid] = ((const ulonglong2*)rowB)[24 + g];
        }
    } else {
        #pragma unroll
        for (int g = 0; g < 24; g++) {
            int j = j0 + 4 * g;
            ((float4*)TrA)[g] = make_float4(Tm[(j+0)*S + u],       Tm[(j+1)*S + u],
                                            Tm[(j+2)*S + u],       Tm[(j+3)*S + u]);
            ((float4*)TrB)[g] = make_float4(Tm[(j+0)*S + u + 128], Tm[(j+1)*S + u + 128],
                                            Tm[(j+2)*S + u + 128], Tm[(j+3)*S + u + 128]);
        }
        #pragma unroll
        for (int g = 0; g < 8; g++) {
            int j = j0 + 96 + 4 * g;
            float4 a4 = make_float4(Tm[(j+0)*S + u],       Tm[(j+1)*S + u],
                                    Tm[(j+2)*S + u],       Tm[(j+3)*S + u]);
            float4 b4 = make_float4(Tm[(j+0)*S + u + 128], Tm[(j+1)*S + u + 128],
                                    Tm[(j+2)*S + u + 128], Tm[(j+3)*S + u + 128]);
            TsmU2[g * 256 + tid]       = *reinterpret_cast<ulonglong2*>(&a4);
            TsmU2[(8 + g) * 256 + tid] = *reinterpret_cast<ulonglong2*>(&b4);
        }
    }

    float* outg = bwd ? g_bwd : g_fwd;

    // --- step 0 ---
    const int t0 = bwd ? (L - 1) : 0;
    {
        float e0 = emb[tok[t0] * S + tid];
        float e1 = emb[tok[256 + t0] * S + tid];
        if (!bwd) {
            outg[(t0 * NB + b0) * S + tid] = 1.0f;    // fprime[0] = 1
            outg[(t0 * NB + b1) * S + tid] = 1.0f;
        } else {
            outg[(t0 * NB + b0) * S + tid] = e0;      // b[L-1] = e[L-1]
            outg[(t0 * NB + b1) * S + tid] = e1;
        }
        xs[tid]       = e0;
        xs[256 + tid] = e1;
    }
    __syncthreads();

    const int dt = bwd ? -1 : 1;
    int t = t0;
    int p = 0;

    // deferred-output registers
    float o0 = 0.f, o1 = 0.f;
    int   tprev = -1;

    for (int step = 1; step < L; step++) {
        t += dt;

        // deferred output write from previous step (overlaps this matvec)
        if (tprev >= 0) {
            outg[(tprev * NB + b0) * S + tid] = o0;
            outg[(tprev * NB + b1) * S + tid] = o1;
        }

        // e prefetch: consumed only after bar1
        float en0 = emb[tok[t] * S + tid];
        float en1 = emb[tok[256 + t] * S + tid];

        const ulonglong2* X0 = (const ulonglong2*)(xs + p * 512 + j0);
        const ulonglong2* X1 = (const ulonglong2*)(xs + p * 512 + 256 + j0);

        ull a00l = 0, a00h = 0, a01l = 0, a01h = 0;   // state u:     chain0, chain1
        ull a10l = 0, a10h = 0, a11l = 0, a11h = 0;   // state u+128

        #pragma unroll
        for (int g = 0; g < 24; g++) {
            ulonglong2 x0 = X0[g];
            ulonglong2 x1 = X1[g];
            ffma2(a00l, TrA[2*g],   x0.x); ffma2(a00h, TrA[2*g+1], x0.y);
            ffma2(a01l, TrA[2*g],   x1.x); ffma2(a01h, TrA[2*g+1], x1.y);
            ffma2(a10l, TrB[2*g],   x0.x); ffma2(a10h, TrB[2*g+1], x0.y);
            ffma2(a11l, TrB[2*g],   x1.x); ffma2(a11h, TrB[2*g+1], x1.y);
        }
        #pragma unroll
        for (int g = 0; g < 8; g++) {
            ulonglong2 tA = TsmU2[g * 256 + tid];
            ulonglong2 tB = TsmU2[(8 + g) * 256 + tid];
            ulonglong2 x0 = X0[24 + g];
            ulonglong2 x1 = X1[24 + g];
            ffma2(a00l, tA.x, x0.x); ffma2(a00h, tA.y, x0.y);
            ffma2(a01l, tA.x, x1.x); ffma2(a01h, tA.y, x1.y);
            ffma2(a10l, tB.x, x0.x); ffma2(a10h, tB.y, x0.y);
            ffma2(a11l, tB.x, x1.x); ffma2(a11h, tB.y, x1.y);
        }

        // partials: part[c][h][s]
        part[h * 256 + u]             = hsum2(a00l, a00h);
        part[h * 256 + u + 128]       = hsum2(a10l, a10h);
        part[512 + h * 256 + u]       = hsum2(a01l, a01h);
        part[512 + h * 256 + u + 128] = hsum2(a11l, a11h);
        __syncthreads();

        // combine: thread tid handles state tid, both chains
        float s0 = part[tid]       + part[256 + tid];
        float s1 = part[512 + tid] + part[768 + tid];
        float nx0 = s0 * en0;
        float nx1 = s1 * en1;

        // stash outputs for deferred write (after bar2)
        o0 = bwd ? nx0 : s0;
        o1 = bwd ? nx1 : s1;
        tprev = t;

        p ^= 1;
        xs[p * 512 + tid]       = nx0;
        xs[p * 512 + 256 + tid] = nx1;
        __syncthreads();
    }

    // final deferred write
    outg[(tprev * NB + b0) * S + tid] = o0;
    outg[(tprev * NB + b1) * S + tid] = o1;
}

// ---------------------------------------------------------------------------
// K2 — v2 exact (fastest measured: 34.8us): 256 CTAs, tile = 128 rows x
// 64 cols, 8x4 per thread, packed fma.rn.f32x2, 2 sc per iteration with
// float2 broadcast e-loads.
// ---------------------------------------------------------------------------
__global__ __launch_bounds__(256, 2)
void hmm_proj_kernel(const float* __restrict__ Om, float* __restrict__ outp)
{
    extern __shared__ char smem2[];
    float* esm = (float*)smem2;                  // [128][68]
    float* osm = (float*)(smem2 + 128*68*4);     // [64][64]

    const int tid = threadIdx.x;
    const int r0  = blockIdx.x * 128;
    const int rg  = tid >> 4;
    const int cg  = tid & 15;

    ull acc01[8] = {0,0,0,0,0,0,0,0};
    ull acc23[8] = {0,0,0,0,0,0,0,0};

    for (int s0 = 0; s0 < S; s0 += 64) {
        if (s0) __syncthreads();
        #pragma unroll
        for (int k = 0; k < 8; k++) {
            int id4 = k * 256 + tid;
            int rr  = id4 >> 4;
            int ss  = (id4 & 15) * 4;
            int r   = r0 + rr;
            float4 fv = *(const float4*)&g_fwd[r * S + s0 + ss];
            float4 bv = *(const float4*)&g_bwd[r * S + s0 + ss];
            float4 ev = make_float4(fv.x * bv.x, fv.y * bv.y, fv.z * bv.z, fv.w * bv.w);
            *(float4*)&esm[rr * 68 + ss] = ev;
        }
        #pragma unroll
        for (int k = 0; k < 4; k++) {
            int id4 = k * 256 + tid;
            int ss  = id4 >> 4;
            int n   = (id4 & 15) * 4;
            *(float4*)&osm[ss * 64 + n] = *(const float4*)&Om[(s0 + ss) * NL + n];
        }
        __syncthreads();

        #pragma unroll 4
        for (int sc = 0; sc < 64; sc += 2) {
            ulonglong2 ov0 = *(const ulonglong2*)&osm[sc * 64 + cg * 4];
            ulonglong2 ov1 = *(const ulonglong2*)&osm[(sc + 1) * 64 + cg * 4];
            #pragma unroll
            for (int k = 0; k < 8; k++) {
                float2 ep = *(const float2*)&esm[(rg * 8 + k) * 68 + sc];
                ull e0 = packdup(ep.x);
                ull e1 = packdup(ep.y);
                ffma2(acc01[k], e0, ov0.x);
                ffma2(acc23[k], e0, ov0.y);
                ffma2(acc01[k], e1, ov1.x);
                ffma2(acc23[k], e1, ov1.y);
            }
        }
    }

    #pragma unroll
    for (int k = 0; k < 8; k++) {
        int r  = r0 + rg * 8 + k;
        int t  = r >> 7;
        int bb = r & 127;
        float2 lo = *reinterpret_cast<float2*>(&acc01[k]);
        float2 hi = *reinterpret_cast<float2*>(&acc23[k]);
        float4 v  = make_float4(lo.x, lo.y, hi.x, hi.y);
        *(float4*)&outp[(bb * L + t) * NL + cg * 4] = v;
    }
}

extern "C" void kernel_launch(void* const* d_in, const int* in_sizes, int n_in,
                              void* d_out, int out_size)
{
    (void)in_sizes; (void)n_in; (void)out_size;
    const void*  sent = d_in[0];
    const float* emb  = (const float*)d_in[1];
    const float* Tm   = (const float*)d_in[2];
    const float* Om   = (const float*)d_in[3];
    float* outp = (float*)d_out;

    cudaFuncSetAttribute(hmm_scan_kernel,
                         cudaFuncAttributeMaxDynamicSharedMemorySize, SMEM1);
    cudaFuncSetAttribute(hmm_proj_kernel,
                         cudaFuncAttributeMaxDynamicSharedMemorySize, SMEM2);

    hmm_scan_kernel<<<128, 256, SMEM1>>>(sent, emb, Tm);
    hmm_proj_kernel<<<256, 256, SMEM2>>>(Om, outp);
}